// round 13
// baseline (speedup 1.0000x reference)
#include <cuda_runtime.h>
#include <cstdint>

// CausalConv1d: x (4, 2048, 8192) f32, depthwise weight (2048, 1, 16), bias (2048)
// out[n,c,l] = sum_{k=0..15} x[n,c,l-15+k] * w[c,0,k] + bias[c]   (zero-pad left)
//
// R12 pipeline + bulk TMA stores: inputs arrive via 8 up-front cp.async.bulk
// g2s tiles (per-stage complete_tx mbarrier). Each stage's 4KB of results is
// staged in a double-buffered smem tile and written with ONE cp.async.bulk
// s2g -> long contiguous write bursts, fewer DRAM R/W turnarounds.

#define DIM    2048
#define LEN    8192
#define KSZ    16
#define BLOCK  256
#define OPT    4
#define TILE   (BLOCK * OPT)      // 1024
#define NST    (LEN / TILE)       // 8 stages
#define STAGEF (TILE + KSZ)       // 1040 floats per stage
#define STAGEB (STAGEF * 4)       // 4160 bytes

__device__ __forceinline__ uint32_t smem_u32(const void* p) {
    return (uint32_t)__cvta_generic_to_shared(p);
}

__device__ __forceinline__ void mbar_init(uint32_t mbar, uint32_t count) {
    asm volatile("mbarrier.init.shared.b64 [%0], %1;" :: "r"(mbar), "r"(count) : "memory");
}

__device__ __forceinline__ void mbar_expect_tx(uint32_t mbar, uint32_t bytes) {
    asm volatile("mbarrier.arrive.expect_tx.shared.b64 _, [%0], %1;"
                 :: "r"(mbar), "r"(bytes) : "memory");
}

__device__ __forceinline__ void bulk_g2s(uint32_t dst, const void* src,
                                         uint32_t bytes, uint32_t mbar) {
    asm volatile(
        "cp.async.bulk.shared::cta.global.mbarrier::complete_tx::bytes [%0], [%1], %2, [%3];"
        :: "r"(dst), "l"(src), "r"(bytes), "r"(mbar) : "memory");
}

__device__ __forceinline__ void bulk_s2g(void* dst, uint32_t src, uint32_t bytes) {
    asm volatile(
        "cp.async.bulk.global.shared::cta.bulk_group [%0], [%1], %2;"
        :: "l"(dst), "r"(src), "r"(bytes) : "memory");
}

__device__ __forceinline__ void bulk_commit() {
    asm volatile("cp.async.bulk.commit_group;" ::: "memory");
}

template <int N>
__device__ __forceinline__ void bulk_wait_read() {
    asm volatile("cp.async.bulk.wait_group.read %0;" :: "n"(N) : "memory");
}

__device__ __forceinline__ void mbar_wait_parity0(uint32_t mbar) {
    uint32_t done;
    asm volatile(
        "{\n\t.reg .pred p;\n\t"
        "mbarrier.try_wait.parity.acquire.cta.shared::cta.b64 p, [%1], 0;\n\t"
        "selp.b32 %0, 1, 0, p;\n\t}"
        : "=r"(done) : "r"(mbar) : "memory");
    if (!done) {
        asm volatile(
            "{\n\t.reg .pred P1;\n\t"
            "WAIT_LOOP_%=:\n\t"
            "mbarrier.try_wait.parity.acquire.cta.shared::cta.b64 P1, [%0], 0, 0x989680;\n\t"
            "@P1 bra.uni WAIT_DONE_%=;\n\t"
            "bra.uni WAIT_LOOP_%=;\n\t"
            "WAIT_DONE_%=:\n\t}"
            :: "r"(mbar) : "memory");
    }
}

__global__ __launch_bounds__(BLOCK, 5) void causal_conv1d_kernel(
    const float* __restrict__ x,
    const float* __restrict__ w,
    const float* __restrict__ bias,
    float* __restrict__ out)
{
    __shared__ alignas(128) float stage[NST][STAGEF];
    __shared__ alignas(128) float obuf[2][TILE];
    __shared__ alignas(8)   unsigned long long mbar[NST];

    const int tid  = threadIdx.x;
    const int wid  = tid >> 5;
    const int lane = tid & 31;
    const int row  = blockIdx.x;
    const int ch   = row & (DIM - 1);            // row = n*DIM + c

    const float* __restrict__ xrow = x   + (size_t)row * LEN;
    float*       __restrict__ orow = out + (size_t)row * LEN;

    // ---- init barriers + zero the 16-float left pad of stage 0 ----
    if (tid < NST) mbar_init(smem_u32(&mbar[tid]), 1);
    if (tid < KSZ / 4) {
        float4 z = make_float4(0.f, 0.f, 0.f, 0.f);
        *reinterpret_cast<float4*>(&stage[0][4 * tid]) = z;
    }
    __syncthreads();

    // ---- producer: lane 0 of warp s issues stage s (parallel prologue) ----
    if (lane == 0) {
        asm volatile("fence.proxy.async.shared::cta;" ::: "memory");
        const int s = wid;
        if (s == 0) {
            mbar_expect_tx(smem_u32(&mbar[0]), TILE * 4);
            bulk_g2s(smem_u32(&stage[0][KSZ]), xrow, TILE * 4, smem_u32(&mbar[0]));
        } else {
            mbar_expect_tx(smem_u32(&mbar[s]), STAGEB);
            bulk_g2s(smem_u32(&stage[s][0]), xrow + s * TILE - KSZ,
                     STAGEB, smem_u32(&mbar[s]));
        }
    }

    // ---- weights + bias (warp-uniform, overlaps TMA) ----
    float wr[KSZ];
    const float4* w4 = reinterpret_cast<const float4*>(w + ch * KSZ);
    #pragma unroll
    for (int q = 0; q < 4; q++) {
        float4 t = w4[q];
        wr[4 * q + 0] = t.x; wr[4 * q + 1] = t.y;
        wr[4 * q + 2] = t.z; wr[4 * q + 3] = t.w;
    }
    const float b = bias[ch];

    // ---- consume stage by stage; write via bulk TMA stores ----
    #pragma unroll
    for (int s = 0; s < NST; s++) {
        mbar_wait_parity0(smem_u32(&mbar[s]));

        // window r[i] = stage[s][4*tid + i], 5 conflict-free LDS.128
        float r[OPT + KSZ];
        const float4* sp = reinterpret_cast<const float4*>(&stage[s][4 * tid]);
        #pragma unroll
        for (int q = 0; q < 5; q++) {
            float4 v = sp[q];
            r[4 * q + 0] = v.x; r[4 * q + 1] = v.y;
            r[4 * q + 2] = v.z; r[4 * q + 3] = v.w;
        }

        float acc[OPT];
        #pragma unroll
        for (int m = 0; m < OPT; m++) {
            float a = b;
            #pragma unroll
            for (int k = 0; k < KSZ; k++)
                a = fmaf(wr[k], r[m + 1 + k], a);
            acc[m] = a;
        }

        const int buf = s & 1;

        // buffer reuse safety: the bulk store issued 2 stages ago must have
        // finished READING obuf[buf] before we overwrite it.
        if (s >= 2) {
            if (tid == 0) bulk_wait_read<1>();
            __syncthreads();
        }

        float4 ov; ov.x = acc[0]; ov.y = acc[1]; ov.z = acc[2]; ov.w = acc[3];
        *reinterpret_cast<float4*>(&obuf[buf][4 * tid]) = ov;
        __syncthreads();

        if (tid == 0) {
            asm volatile("fence.proxy.async.shared::cta;" ::: "memory");
            bulk_s2g(orow + s * TILE, smem_u32(&obuf[buf][0]), TILE * 4);
            bulk_commit();
        }
    }

    // ensure all bulk stores are complete before the CTA retires
    if (tid == 0) bulk_wait_read<0>();
}

extern "C" void kernel_launch(void* const* d_in, const int* in_sizes, int n_in,
                              void* d_out, int out_size)
{
    const float* x    = (const float*)d_in[0];
    const float* w    = (const float*)d_in[1];
    const float* bias = (const float*)d_in[2];
    float* out        = (float*)d_out;

    const int blocks = 4 * DIM;                  // 8192 rows
    causal_conv1d_kernel<<<blocks, BLOCK>>>(x, w, bias, out);
}

// round 14
// speedup vs baseline: 1.0117x; 1.0117x over previous
#include <cuda_runtime.h>
#include <cstdint>

// CausalConv1d: x (4, 2048, 8192) f32, depthwise weight (2048, 1, 16), bias (2048)
// out[n,c,l] = sum_{k=0..15} x[n,c,l-15+k] * w[c,0,k] + bias[c]   (zero-pad left)
//
// R12 (best: 82.5us) + L2::evict_first on the input TMA stream: input bytes
// have zero L2 reuse, so marking them evict-first leaves more L2 capacity to
// aggregate the write stream into long DRAM bursts. Otherwise identical:
// one block per row, 8 up-front cp.async.bulk tiles (warp s issues stage s),
// 5 conflict-free LDS.128 + 64 FMA + st.global.cs per stage, 5 blocks/SM.

#define DIM    2048
#define LEN    8192
#define KSZ    16
#define BLOCK  256
#define OPT    4
#define TILE   (BLOCK * OPT)      // 1024
#define NST    (LEN / TILE)       // 8 stages
#define STAGEF (TILE + KSZ)       // 1040 floats per stage
#define STAGEB (STAGEF * 4)       // 4160 bytes

__device__ __forceinline__ uint32_t smem_u32(const void* p) {
    return (uint32_t)__cvta_generic_to_shared(p);
}

__device__ __forceinline__ void mbar_init(uint32_t mbar, uint32_t count) {
    asm volatile("mbarrier.init.shared.b64 [%0], %1;" :: "r"(mbar), "r"(count) : "memory");
}

__device__ __forceinline__ void mbar_expect_tx(uint32_t mbar, uint32_t bytes) {
    asm volatile("mbarrier.arrive.expect_tx.shared.b64 _, [%0], %1;"
                 :: "r"(mbar), "r"(bytes) : "memory");
}

__device__ __forceinline__ uint64_t l2_evict_first_policy() {
    uint64_t pol;
    asm("createpolicy.fractional.L2::evict_first.b64 %0, 1.0;" : "=l"(pol));
    return pol;
}

__device__ __forceinline__ void bulk_g2s_hint(uint32_t dst, const void* src,
                                              uint32_t bytes, uint32_t mbar,
                                              uint64_t pol) {
    asm volatile(
        "cp.async.bulk.shared::cta.global.mbarrier::complete_tx::bytes.L2::cache_hint"
        " [%0], [%1], %2, [%3], %4;"
        :: "r"(dst), "l"(src), "r"(bytes), "r"(mbar), "l"(pol) : "memory");
}

__device__ __forceinline__ void mbar_wait_parity0(uint32_t mbar) {
    uint32_t done;
    asm volatile(
        "{\n\t.reg .pred p;\n\t"
        "mbarrier.try_wait.parity.acquire.cta.shared::cta.b64 p, [%1], 0;\n\t"
        "selp.b32 %0, 1, 0, p;\n\t}"
        : "=r"(done) : "r"(mbar) : "memory");
    if (!done) {
        asm volatile(
            "{\n\t.reg .pred P1;\n\t"
            "WAIT_LOOP_%=:\n\t"
            "mbarrier.try_wait.parity.acquire.cta.shared::cta.b64 P1, [%0], 0, 0x989680;\n\t"
            "@P1 bra.uni WAIT_DONE_%=;\n\t"
            "bra.uni WAIT_LOOP_%=;\n\t"
            "WAIT_DONE_%=:\n\t}"
            :: "r"(mbar) : "memory");
    }
}

__device__ __forceinline__ void stg_cs_v4(float* p, float a, float b, float c, float d) {
    asm volatile("st.global.cs.v4.f32 [%0], {%1, %2, %3, %4};"
                 :: "l"(p), "f"(a), "f"(b), "f"(c), "f"(d) : "memory");
}

__global__ __launch_bounds__(BLOCK, 5) void causal_conv1d_kernel(
    const float* __restrict__ x,
    const float* __restrict__ w,
    const float* __restrict__ bias,
    float* __restrict__ out)
{
    __shared__ alignas(128) float stage[NST][STAGEF];
    __shared__ alignas(8)   unsigned long long mbar[NST];

    const int tid  = threadIdx.x;
    const int wid  = tid >> 5;
    const int lane = tid & 31;
    const int row  = blockIdx.x;
    const int ch   = row & (DIM - 1);            // row = n*DIM + c

    const float* __restrict__ xrow = x   + (size_t)row * LEN;
    float*       __restrict__ orow = out + (size_t)row * LEN;

    // ---- init barriers + zero the 16-float left pad of stage 0 ----
    if (tid < NST) mbar_init(smem_u32(&mbar[tid]), 1);
    if (tid < KSZ / 4) {
        float4 z = make_float4(0.f, 0.f, 0.f, 0.f);
        *reinterpret_cast<float4*>(&stage[0][4 * tid]) = z;
    }
    __syncthreads();

    // ---- producer: lane 0 of warp s issues stage s (parallel prologue) ----
    if (lane == 0) {
        asm volatile("fence.proxy.async.shared::cta;" ::: "memory");
        const uint64_t pol = l2_evict_first_policy();
        const int s = wid;
        if (s == 0) {
            // stage 0: data lands at offset 16 (halo is the zero pad)
            mbar_expect_tx(smem_u32(&mbar[0]), TILE * 4);
            bulk_g2s_hint(smem_u32(&stage[0][KSZ]), xrow, TILE * 4,
                          smem_u32(&mbar[0]), pol);
        } else {
            mbar_expect_tx(smem_u32(&mbar[s]), STAGEB);
            bulk_g2s_hint(smem_u32(&stage[s][0]), xrow + s * TILE - KSZ,
                          STAGEB, smem_u32(&mbar[s]), pol);
        }
    }

    // ---- weights + bias (warp-uniform, overlaps TMA) ----
    float wr[KSZ];
    const float4* w4 = reinterpret_cast<const float4*>(w + ch * KSZ);
    #pragma unroll
    for (int q = 0; q < 4; q++) {
        float4 t = w4[q];
        wr[4 * q + 0] = t.x; wr[4 * q + 1] = t.y;
        wr[4 * q + 2] = t.z; wr[4 * q + 3] = t.w;
    }
    const float b = bias[ch];

    // ---- consume stage by stage ----
    #pragma unroll
    for (int s = 0; s < NST; s++) {
        mbar_wait_parity0(smem_u32(&mbar[s]));

        // window r[i] = xrow[s*TILE - 16 + 4*tid + i] = stage[s][4*tid + i]
        float r[OPT + KSZ];
        const float4* sp = reinterpret_cast<const float4*>(&stage[s][4 * tid]);
        #pragma unroll
        for (int q = 0; q < 5; q++) {
            float4 v = sp[q];
            r[4 * q + 0] = v.x; r[4 * q + 1] = v.y;
            r[4 * q + 2] = v.z; r[4 * q + 3] = v.w;
        }

        float acc[OPT];
        #pragma unroll
        for (int m = 0; m < OPT; m++) {
            float a = b;
            #pragma unroll
            for (int k = 0; k < KSZ; k++)
                a = fmaf(wr[k], r[m + 1 + k], a);
            acc[m] = a;
        }

        stg_cs_v4(orow + s * TILE + 4 * tid, acc[0], acc[1], acc[2], acc[3]);
    }
}

extern "C" void kernel_launch(void* const* d_in, const int* in_sizes, int n_in,
                              void* d_out, int out_size)
{
    const float* x    = (const float*)d_in[0];
    const float* w    = (const float*)d_in[1];
    const float* bias = (const float*)d_in[2];
    float* out        = (float*)d_out;

    const int blocks = 4 * DIM;                  // 8192 rows
    causal_conv1d_kernel<<<blocks, BLOCK>>>(x, w, bias, out);
}